// round 1
// baseline (speedup 1.0000x reference)
#include <cuda_runtime.h>

// Radon forward projection: out[b,a,s] = sum_t bilinear(imgs[b], x(s,t), y(s,t))
// x = s*cos - t*sin + c ; y = s*sin + t*cos + c ; c = 127.5, s,t centered.
//
// Strategy: block = (b, pair of angles). Image half staged in SMEM with zero
// guard borders; two phases cover y-halves. Branchless bilinear via guard
// zeros + integer clamp. 512 threads = 2 angles x 256 detectors.

#define B_ 8
#define N_ 256
#define A_ 180

constexpr int STRIDE = 261;                 // 260 cols (-2..257) + 1 pad; odd -> bank-friendly
constexpr int TROWS  = 130;                 // max rows per phase tile (incl. guards)
constexpr int SMEM_WORDS = STRIDE * TROWS;  // 33,930 floats = 135,720 B

__global__ __launch_bounds__(512, 1)
void radon_kernel(const float* __restrict__ imgs,
                  const float* __restrict__ angles,
                  float* __restrict__ out)
{
    extern __shared__ float tile[];
    const int tid  = threadIdx.x;
    const int blk  = blockIdx.x;
    const int b    = blk / (A_ / 2);
    const int ap   = blk % (A_ / 2);
    const int al   = tid >> 8;          // 0/1: which angle of the pair
    const int s    = tid & 255;         // detector index
    const int a    = ap * 2 + al;

    const float ang = angles[a];
    const float ca  = cosf(ang);
    const float sa  = sinf(ang);
    const float sf  = (float)s - 127.5f;
    const float xs  = fmaf(sf, ca, 127.5f);   // x at t-center offset 0
    const float ys  = fmaf(sf, sa, 127.5f);
    const float nsa = -sa;

    const float* __restrict__ img = imgs + b * N_ * N_;

    float acc = 0.0f;

    #pragma unroll
    for (int phase = 0; phase < 2; ++phase) {
        if (phase) __syncthreads();     // protect restage vs prior compute

        // ---- stage: zero whole tile (covers guard rows/cols), then fill real rows
        for (int i = tid; i < SMEM_WORDS; i += 512) tile[i] = 0.0f;
        __syncthreads();

        // phase 0: tile rows represent image rows -1..128 (row -1 = zeros)
        // phase 1: tile rows represent image rows 128..256 (row 256 = zeros)
        const int row_base = phase ? 128 : -1;     // image row of tile row 0
        const int r_first  = phase ? 128 : 0;      // first real image row
        const int nr       = phase ? 128 : 129;    // real rows staged
        for (int i = tid; i < nr * N_; i += 512) {
            int rr = i >> 8;
            int cc = i & 255;
            tile[(r_first - row_base + rr) * STRIDE + cc + 2] =
                img[(r_first + rr) * N_ + cc];
        }
        __syncthreads();

        // ---- accumulate samples whose y0 falls in this phase's row range
        const int      v_lo = phase ? 128  : -1;   // valid y0i range
        const unsigned span = phase ? 127u : 128u;
        const float* __restrict__ tb = tile + 2 - row_base * STRIDE;

        #pragma unroll 4
        for (int t = 0; t < N_; ++t) {
            float tf = (float)t - 127.5f;
            float y  = fmaf(tf, ca, ys);
            int y0i  = __float2int_rd(y);
            if ((unsigned)(y0i - v_lo) > span) continue;   // other phase / fully OOB

            float x  = fmaf(tf, nsa, xs);
            int x0i  = __float2int_rd(x);
            float wx = x - (float)x0i;
            float wy = y - (float)y0i;

            // clamp into guard region: cols -2,-1,256,257 are zeros, so any
            // fully-OOB x contributes exactly 0 regardless of weights.
            int xc = min(max(x0i, -2), 256);

            const float* p = tb + y0i * STRIDE + xc;
            float a00 = p[0];
            float a01 = p[1];
            float a10 = p[STRIDE];
            float a11 = p[STRIDE + 1];

            float h0 = fmaf(wx, a01 - a00, a00);
            float h1 = fmaf(wx, a11 - a10, a10);
            acc += fmaf(wy, h1 - h0, h0);
        }
    }

    out[(b * A_ + a) * N_ + s] = acc;
}

extern "C" void kernel_launch(void* const* d_in, const int* in_sizes, int n_in,
                              void* d_out, int out_size)
{
    const float* imgs   = (const float*)d_in[0];
    const float* angles = (const float*)d_in[1];
    float*       out    = (float*)d_out;

    cudaFuncSetAttribute(radon_kernel,
                         cudaFuncAttributeMaxDynamicSharedMemorySize,
                         SMEM_WORDS * (int)sizeof(float));

    const int blocks = B_ * (A_ / 2);   // 720
    radon_kernel<<<blocks, 512, SMEM_WORDS * sizeof(float)>>>(imgs, angles, out);
}

// round 2
// speedup vs baseline: 1.0002x; 1.0002x over previous
#include <cuda_runtime.h>

// Radon forward projection: out[b,a,s] = sum_t bilinear(imgs[b], x(s,t), y(s,t))
// x = s*cos - t*sin + c ; y = s*sin + t*cos + c ; c = 127.5, s,t centered.
//
// Strategy: block = (b, pair of angles). Image half staged in SMEM with zero
// guard borders; two phases cover y-halves. Branchless bilinear via guard
// zeros + integer clamp. 512 threads = 2 angles x 256 detectors.

#define B_ 8
#define N_ 256
#define A_ 180

constexpr int STRIDE = 261;                 // 260 cols (-2..257) + 1 pad; odd -> bank-friendly
constexpr int TROWS  = 130;                 // max rows per phase tile (incl. guards)
constexpr int SMEM_WORDS = STRIDE * TROWS;  // 33,930 floats = 135,720 B

__global__ __launch_bounds__(512, 1)
void radon_kernel(const float* __restrict__ imgs,
                  const float* __restrict__ angles,
                  float* __restrict__ out)
{
    extern __shared__ float tile[];
    const int tid  = threadIdx.x;
    const int blk  = blockIdx.x;
    const int b    = blk / (A_ / 2);
    const int ap   = blk % (A_ / 2);
    const int al   = tid >> 8;          // 0/1: which angle of the pair
    const int s    = tid & 255;         // detector index
    const int a    = ap * 2 + al;

    const float ang = angles[a];
    const float ca  = cosf(ang);
    const float sa  = sinf(ang);
    const float sf  = (float)s - 127.5f;
    const float xs  = fmaf(sf, ca, 127.5f);   // x at t-center offset 0
    const float ys  = fmaf(sf, sa, 127.5f);
    const float nsa = -sa;

    const float* __restrict__ img = imgs + b * N_ * N_;

    float acc = 0.0f;

    #pragma unroll
    for (int phase = 0; phase < 2; ++phase) {
        if (phase) __syncthreads();     // protect restage vs prior compute

        // ---- stage: zero whole tile (covers guard rows/cols), then fill real rows
        for (int i = tid; i < SMEM_WORDS; i += 512) tile[i] = 0.0f;
        __syncthreads();

        // phase 0: tile rows represent image rows -1..128 (row -1 = zeros)
        // phase 1: tile rows represent image rows 128..256 (row 256 = zeros)
        const int row_base = phase ? 128 : -1;     // image row of tile row 0
        const int r_first  = phase ? 128 : 0;      // first real image row
        const int nr       = phase ? 128 : 129;    // real rows staged
        for (int i = tid; i < nr * N_; i += 512) {
            int rr = i >> 8;
            int cc = i & 255;
            tile[(r_first - row_base + rr) * STRIDE + cc + 2] =
                img[(r_first + rr) * N_ + cc];
        }
        __syncthreads();

        // ---- accumulate samples whose y0 falls in this phase's row range
        const int      v_lo = phase ? 128  : -1;   // valid y0i range
        const unsigned span = phase ? 127u : 128u;
        const float* __restrict__ tb = tile + 2 - row_base * STRIDE;

        #pragma unroll 4
        for (int t = 0; t < N_; ++t) {
            float tf = (float)t - 127.5f;
            float y  = fmaf(tf, ca, ys);
            int y0i  = __float2int_rd(y);
            if ((unsigned)(y0i - v_lo) > span) continue;   // other phase / fully OOB

            float x  = fmaf(tf, nsa, xs);
            int x0i  = __float2int_rd(x);
            float wx = x - (float)x0i;
            float wy = y - (float)y0i;

            // clamp into guard region: cols -2,-1,256,257 are zeros, so any
            // fully-OOB x contributes exactly 0 regardless of weights.
            int xc = min(max(x0i, -2), 256);

            const float* p = tb + y0i * STRIDE + xc;
            float a00 = p[0];
            float a01 = p[1];
            float a10 = p[STRIDE];
            float a11 = p[STRIDE + 1];

            float h0 = fmaf(wx, a01 - a00, a00);
            float h1 = fmaf(wx, a11 - a10, a10);
            acc += fmaf(wy, h1 - h0, h0);
        }
    }

    out[(b * A_ + a) * N_ + s] = acc;
}

extern "C" void kernel_launch(void* const* d_in, const int* in_sizes, int n_in,
                              void* d_out, int out_size)
{
    const float* imgs   = (const float*)d_in[0];
    const float* angles = (const float*)d_in[1];
    float*       out    = (float*)d_out;

    cudaFuncSetAttribute(radon_kernel,
                         cudaFuncAttributeMaxDynamicSharedMemorySize,
                         SMEM_WORDS * (int)sizeof(float));

    const int blocks = B_ * (A_ / 2);   // 720
    radon_kernel<<<blocks, 512, SMEM_WORDS * sizeof(float)>>>(imgs, angles, out);
}

// round 4
// speedup vs baseline: 1.1266x; 1.1264x over previous
#include <cuda_runtime.h>

// Radon forward projection: out[b,a,s] = sum_t bilinear(imgs[b], x(s,t), y(s,t))
// x = s*cos - t*sin + c ; y = s*sin + t*cos + c ; c = 127.5.
//
// Block = (image b, pair of angles), 512 threads = 2 angles x 256 detectors.
// Image covered in 4 y-phases of 64 rows; each phase stages a 66-row tile
// (1 guard row each side, 2 guard cols each side, zeros) in 68.9 KB SMEM
// -> 3 CTAs/SM. Phase ownership decided by EXACT float compares on the same
// fmaf-computed y used for indexing (y0i in [L,U-1] <=> y in [L,U), L,U ints),
// exploiting monotonicity of y(t): skip until band entered, break once passed.

#define B_ 8
#define N_ 256
#define A_ 180

constexpr int STRIDE     = 261;              // 260 cols (-2..257) + 1 pad, odd stride
constexpr int TROWS      = 66;               // 64 band rows + 1 guard each side
constexpr int SMEM_WORDS = STRIDE * TROWS;   // 17,226 floats = 68,904 B
constexpr int PHASES     = 4;

__global__ __launch_bounds__(512, 3)
void radon_kernel(const float* __restrict__ imgs,
                  const float* __restrict__ angles,
                  float* __restrict__ out)
{
    extern __shared__ float tile[];
    const int tid = threadIdx.x;
    const int b   = blockIdx.x / (A_ / 2);
    const int ap  = blockIdx.x % (A_ / 2);
    const int al  = tid >> 8;          // which angle of the pair
    const int s   = tid & 255;         // detector index
    const int a   = ap * 2 + al;

    const float ang = angles[a];
    const float ca  = cosf(ang);
    const float sa  = sinf(ang);
    const float sf  = (float)s - 127.5f;
    const float xs  = fmaf(sf, ca, 127.5f);
    const float ys  = fmaf(sf, sa, 127.5f);
    const float nsa = -sa;
    const bool  up  = (ca >= 0.0f);    // y non-decreasing in t?

    // y range endpoints (exact same fmaf form as the loop)
    const float yA   = fmaf(-127.5f, ca, ys);
    const float yB   = fmaf( 127.5f, ca, ys);
    const float ymin = fminf(yA, yB);
    const float ymax = fmaxf(yA, yB);

    const float* __restrict__ img = imgs + b * N_ * N_;
    float acc = 0.0f;

    #pragma unroll 1
    for (int p = 0; p < PHASES; ++p) {
        if (p) __syncthreads();                 // protect restage vs prior reads
        const int base = 64 * p - 1;            // image row of tile row 0

        // ---- stage tile (single pass, guards get zeros)
        for (int i = tid; i < SMEM_WORDS; i += 512) {
            int r  = i / STRIDE;
            int c  = i - r * STRIDE;
            int ir = base + r;
            int ic = c - 2;
            float v = 0.0f;
            if ((unsigned)ir < (unsigned)N_ && (unsigned)ic < (unsigned)N_)
                v = img[ir * N_ + ic];
            tile[i] = v;
        }
        __syncthreads();

        // Owned band: y0i in [L, U-1]  <=>  y in [L, U)   (exact for integer L,U)
        const float L = (p == 0) ? -1.0f : (float)(64 * p);
        const float U = (float)(64 * (p + 1));

        if (ymax >= L && ymin < U) {
            #pragma unroll 2
            for (int t = 0; t < N_; ++t) {
                float tf = (float)t - 127.5f;
                float y  = fmaf(tf, ca, ys);

                // monotone y: prefix = before band, suffix = past band
                if (up ? (y >= U) : (y < L)) break;      // passed band: done
                if (up ? (y <  L) : (y >= U)) continue;  // not reached yet

                float x  = fmaf(tf, nsa, xs);
                float fy = floorf(y);
                float fx = floorf(x);
                int x0i  = (int)fx;
                float wy = y - fy;
                float wx = x - fx;

                int xc = min(max(x0i, -2), 256) + 2;     // guard cols are zero
                int yr = (int)fy - base;                 // in [0,64] (owned)

                const float* ptr = tile + yr * STRIDE + xc;
                float a00 = ptr[0];
                float a01 = ptr[1];
                float a10 = ptr[STRIDE];
                float a11 = ptr[STRIDE + 1];

                float h0 = fmaf(wx, a01 - a00, a00);
                float h1 = fmaf(wx, a11 - a10, a10);
                acc += fmaf(wy, h1 - h0, h0);
            }
        }
    }

    out[(b * A_ + a) * N_ + s] = acc;
}

extern "C" void kernel_launch(void* const* d_in, const int* in_sizes, int n_in,
                              void* d_out, int out_size)
{
    const float* imgs   = (const float*)d_in[0];
    const float* angles = (const float*)d_in[1];
    float*       out    = (float*)d_out;

    cudaFuncSetAttribute(radon_kernel,
                         cudaFuncAttributeMaxDynamicSharedMemorySize,
                         SMEM_WORDS * (int)sizeof(float));

    const int blocks = B_ * (A_ / 2);   // 720
    radon_kernel<<<blocks, 512, SMEM_WORDS * sizeof(float)>>>(imgs, angles, out);
}

// round 5
// speedup vs baseline: 1.7534x; 1.5564x over previous
#include <cuda_runtime.h>

// Radon forward projection: out[b,a,s] = sum_t bilinear(imgs[b], x(s,t), y(s,t))
// x = s*cos - t*sin + c ; y = s*sin + t*cos + c ; c = 127.5.
//
// Block = (image b, pair of angles), 512 threads = 2 angles x 256 detectors.
// 4 y-phases of 64 rows; each phase stages a 66-row tile (guard row each side,
// 2 guard cols each side, zeros) in 68.9 KB SMEM -> 3 CTAs/SM.
// Ownership stays EXACT: in-band <=> L <= y < U with y = fmaf(tf,ca,ys) and
// integer L,U; analytic (conservative, pad-2) t entry + x-window only skip
// iterations that are provably not-owned / provably zero-contribution.

#define B_ 8
#define N_ 256
#define A_ 180

constexpr int STRIDE     = 261;              // 260 cols (-2..257) + 1 pad, odd stride
constexpr int TROWS      = 66;               // 64 band rows + 1 guard each side
constexpr int SMEM_WORDS = STRIDE * TROWS;   // 17,226 floats = 68,904 B
constexpr int PHASES     = 4;

__global__ __launch_bounds__(512, 3)
void radon_kernel(const float* __restrict__ imgs,
                  const float* __restrict__ angles,
                  float* __restrict__ out)
{
    extern __shared__ float tile[];
    const int tid  = threadIdx.x;
    const int b    = blockIdx.x / (A_ / 2);
    const int ap   = blockIdx.x % (A_ / 2);
    const int al   = tid >> 8;          // which angle of the pair
    const int s    = tid & 255;         // detector index
    const int a    = ap * 2 + al;
    const int warp = tid >> 5;
    const int lane = tid & 31;

    const float ang = angles[a];
    const float ca  = cosf(ang);
    const float sa  = sinf(ang);
    const float sf  = (float)s - 127.5f;
    const float xs  = fmaf(sf, ca, 127.5f);
    const float ys  = fmaf(sf, sa, 127.5f);
    const float nsa = -sa;
    const bool  up  = (ca >= 0.0f);     // y non-decreasing in t?

    // y endpoints (same fmaf form as the loop) for phase pre-check
    const float yA   = fmaf(-127.5f, ca, ys);
    const float yB   = fmaf( 127.5f, ca, ys);
    const float ymin = fminf(yA, yB);
    const float ymax = fmaxf(yA, yB);

    // analytic helpers (conservative only; exactness comes from in-loop tests)
    const float inv_ca = 1.0f / ((ca == 0.0f) ? 1e-30f : ca);
    const float inv_sa = 1.0f / ((sa == 0.0f) ? 1e-30f : sa);

    // x-window: keep t where x could be > -3 and < 259 (pad 2 beyond the
    // exact zero-contribution bound x in [-1, 257)). Outside -> x0i <= -2 or
    // >= 256 -> both sampled cols are guard zeros -> contribution exactly 0.
    float tca = (xs + 3.0f)   * inv_sa;   // t offset where x = -3
    float tcb = (xs - 259.0f) * inv_sa;   // t offset where x = 259
    float txlo_f = fminf(tca, tcb) + 127.5f;
    float txhi_f = fmaxf(tca, tcb) + 127.5f;
    const int txlo = (int)fmaxf(floorf(txlo_f) - 2.0f, 0.0f);
    const int txhi = (int)fminf(ceilf (txhi_f) + 2.0f, 255.0f);

    const float* __restrict__ img = imgs + b * N_ * N_;
    float acc = 0.0f;

    #pragma unroll 1
    for (int p = 0; p < PHASES; ++p) {
        if (p) __syncthreads();                 // protect restage vs prior reads
        const int base = 64 * p - 1;            // image row of tile row 0

        // ---- stage tile: warp per row, lanes over columns (no division)
        for (int r = warp; r < TROWS; r += 16) {
            const int ir = base + r;
            float* dst = tile + r * STRIDE;
            if ((unsigned)ir < (unsigned)N_) {
                const float* src = img + ir * N_;
                for (int c = lane; c < STRIDE; c += 32) {
                    int ic = c - 2;
                    dst[c] = ((unsigned)ic < (unsigned)N_) ? src[ic] : 0.0f;
                }
            } else {
                for (int c = lane; c < STRIDE; c += 32) dst[c] = 0.0f;
            }
        }
        __syncthreads();

        // Owned band: y0i in [L, U-1]  <=>  y in [L, U)  (exact, integer L,U)
        const float L = (p == 0) ? -1.0f : (float)(64 * p);
        const float U = (float)(64 * (p + 1));
        if (ymax < L || ymin >= U) continue;

        // conservative analytic entry (pad -2, never late)
        const float Lb = up ? L : U;
        float t_ent = fmaf(Lb - ys, inv_ca, 127.5f);
        int t = max((int)fmaxf(floorf(t_ent) - 2.0f, 0.0f), txlo);
        const int t1 = txhi;
        float tf = (float)t - 127.5f;

        // exact entry scan: advance until y enters the band (<= ~4 iters)
        for (; t <= t1; ++t, tf += 1.0f) {
            float y = fmaf(tf, ca, ys);
            if (up ? (y >= L) : (y < U)) break;
        }

        // main loop: only the exit test remains
        #pragma unroll 2
        for (; t <= t1; ++t, tf += 1.0f) {
            float y = fmaf(tf, ca, ys);
            if (up ? (y >= U) : (y < L)) break;   // passed band: done

            float x  = fmaf(tf, nsa, xs);
            float fy = floorf(y);
            float fx = floorf(x);
            int x0i  = (int)fx;
            float wy = y - fy;
            float wx = x - fx;

            int xc = min(max(x0i, -2), 256) + 2;  // guard cols are zero
            int yr = (int)fy - base;              // in [0,64] (owned)

            const float* ptr = tile + yr * STRIDE + xc;
            float a00 = ptr[0];
            float a01 = ptr[1];
            float a10 = ptr[STRIDE];
            float a11 = ptr[STRIDE + 1];

            float h0 = fmaf(wx, a01 - a00, a00);
            float h1 = fmaf(wx, a11 - a10, a10);
            acc += fmaf(wy, h1 - h0, h0);
        }
    }

    out[(b * A_ + a) * N_ + s] = acc;
}

extern "C" void kernel_launch(void* const* d_in, const int* in_sizes, int n_in,
                              void* d_out, int out_size)
{
    const float* imgs   = (const float*)d_in[0];
    const float* angles = (const float*)d_in[1];
    float*       out    = (float*)d_out;

    cudaFuncSetAttribute(radon_kernel,
                         cudaFuncAttributeMaxDynamicSharedMemorySize,
                         SMEM_WORDS * (int)sizeof(float));

    const int blocks = B_ * (A_ / 2);   // 720
    radon_kernel<<<blocks, 512, SMEM_WORDS * sizeof(float)>>>(imgs, angles, out);
}

// round 6
// speedup vs baseline: 1.8605x; 1.0611x over previous
#include <cuda_runtime.h>

// Radon forward projection: out[b,a,s] = sum_t bilinear(imgs[b], x(s,t), y(s,t))
// x = s*cos - t*sin + c ; y = s*sin + t*cos + c ; c = 127.5.
//
// Block = (image b, pair of angles), 512 threads = 2 angles x 256 detectors.
// 4 y-phases of 64 rows; each phase stages a 66-row x 287-col tile (guard row
// each side; 5 zero guard cols left, image cols 5..260, zeros beyond) in
// 75.8 KB SMEM -> 3 CTAs/SM. STRIDE=287 (== -1 mod 32) makes the per-lane
// bank step ca - sa in [-1.42,1.42] -> conflict-free-ish LDS for all angles.
//
// Coordinates are guard-shifted positive: xv = x+5, yv = y+1 (constants folded
// into the fmaf), so (int) truncation == floor and no clamps are needed.
// Ownership is EXACT: band p owns yv in [lo_p, hi_p) with integer float
// bounds, tested on the SAME fmaf(tf,ca,ys1) in every phase (monotone in t:
// skip prefix via entry scan, break once past).

#define B_ 8
#define N_ 256
#define A_ 180

constexpr int STRIDE     = 287;              // == 31 mod 32 -> bank = xi - yr
constexpr int TROWS      = 66;               // 64 band rows + 1 guard each side
constexpr int SMEM_WORDS = STRIDE * TROWS;   // 18,942 floats = 75,768 B
constexpr int PHASES     = 4;

__global__ __launch_bounds__(512, 3)
void radon_kernel(const float* __restrict__ imgs,
                  const float* __restrict__ angles,
                  float* __restrict__ out)
{
    extern __shared__ float tile[];
    const int tid  = threadIdx.x;
    const int b    = blockIdx.x / (A_ / 2);
    const int ap   = blockIdx.x % (A_ / 2);
    const int al   = tid >> 8;          // which angle of the pair
    const int s    = tid & 255;         // detector index
    const int a    = ap * 2 + al;
    const int warp = tid >> 5;
    const int lane = tid & 31;

    const float ang = angles[a];
    const float ca  = cosf(ang);
    const float sa  = sinf(ang);
    const float sf  = (float)s - 127.5f;
    const float xs  = fmaf(sf, ca, 127.5f);
    const float ys  = fmaf(sf, sa, 127.5f);
    const float nsa = -sa;
    const float xs5 = xs + 5.0f;        // guard-shifted x origin
    const float ys1 = ys + 1.0f;        // guard-shifted y origin
    const bool  up  = (ca >= 0.0f);     // yv non-decreasing in t?

    // yv endpoints (same fmaf form as the loop) for exact phase pre-check
    const float yA    = fmaf(-127.5f, ca, ys1);
    const float yB    = fmaf( 127.5f, ca, ys1);
    const float yvmin = fminf(yA, yB);
    const float yvmax = fmaxf(yA, yB);

    // analytic helpers (conservative only; exactness from in-loop tests)
    const float inv_ca = 1.0f / ((ca == 0.0f) ? 1e-30f : ca);
    const float inv_sa = 1.0f / ((sa == 0.0f) ? 1e-30f : sa);

    // x-window: keep t where x in (-3,259), padded +-2 ints. Outside ->
    // x0i <= -2 or >= 256 -> both sampled cols are staged zeros -> exactly 0.
    // Inside-window x stays in (-5.01, 261.01) -> xv = x+5 in (-0.01, 266.01),
    // cols 0..266 < STRIDE, all staged.
    float tca = (xs + 3.0f)   * inv_sa;   // t offset where x = -3
    float tcb = (xs - 259.0f) * inv_sa;   // t offset where x = 259
    float txlo_f = fminf(tca, tcb) + 127.5f;
    float txhi_f = fmaxf(tca, tcb) + 127.5f;
    const int txlo = (int)fmaxf(floorf(txlo_f) - 2.0f, 0.0f);
    const int txhi = (int)fminf(ceilf (txhi_f) + 2.0f, 255.0f);

    const float* __restrict__ img = imgs + b * N_ * N_;
    float acc = 0.0f;

    #pragma unroll 1
    for (int p = 0; p < PHASES; ++p) {
        if (p) __syncthreads();                 // protect restage vs prior reads
        const int base = 64 * p - 1;            // image row of tile row 0

        // ---- stage tile: warp per row, lanes over columns; zeros in guards
        for (int r = warp; r < TROWS; r += 16) {
            const int ir = base + r;
            float* dst = tile + r * STRIDE;
            if ((unsigned)ir < (unsigned)N_) {
                const float* src = img + ir * N_;
                for (int c = lane; c < STRIDE; c += 32) {
                    int ic = c - 5;
                    dst[c] = ((unsigned)ic < (unsigned)N_) ? src[ic] : 0.0f;
                }
            } else {
                for (int c = lane; c < STRIDE; c += 32) dst[c] = 0.0f;
            }
        }
        __syncthreads();

        // Owned band in yv space (yv = y+1): floor(yv) in [lo, hi-1].
        // p=0 owns y0i in [-1,63] -> yv in [0,65); p>0 owns y0i in
        // [64p,64p+63] -> yv in [64p+1, 64p+65). Exact integer float bounds.
        const float lo = (p == 0) ? 0.0f : (float)(64 * p + 1);
        const float hi = (float)(64 * p + 65);
        const int rowoff = 64 * p;              // yr = trunc(yv) - rowoff
        if (yvmax < lo || yvmin >= hi) continue;

        // conservative analytic entry (pad -2, never late; relative fp error)
        const float Lb = up ? lo : hi;
        float t_ent = fmaf(Lb - ys1, inv_ca, 127.5f);
        int t = max((int)fmaxf(fminf(floorf(t_ent) - 2.0f, 255.0f), 0.0f), txlo);
        const int t1 = txhi;
        float tf = (float)t - 127.5f;

        // exact entry scan: advance until yv enters the band
        for (; t <= t1; ++t, tf += 1.0f) {
            float yv = fmaf(tf, ca, ys1);
            if (up ? (yv >= lo) : (yv < hi)) break;
        }

        // main loop: only the exit test remains
        #pragma unroll 2
        for (; t <= t1; ++t, tf += 1.0f) {
            float yv = fmaf(tf, ca, ys1);
            if (up ? (yv >= hi) : (yv < lo)) break;   // passed band: done

            float xv = fmaf(tf, nsa, xs5);
            int yi = (int)yv;                  // trunc == floor (yv >= 0)
            int xi = (int)xv;                  // xv > -0.02: trunc; neg-eps
                                               // lands on zero guard cols
            float wy = yv - (float)yi;
            float wx = xv - (float)xi;

            const float* ptr = tile + (yi - rowoff) * STRIDE + xi;
            float a00 = ptr[0];
            float a01 = ptr[1];
            float a10 = ptr[STRIDE];
            float a11 = ptr[STRIDE + 1];

            float h0 = fmaf(wx, a01 - a00, a00);
            float h1 = fmaf(wx, a11 - a10, a10);
            acc += fmaf(wy, h1 - h0, h0);
        }
    }

    out[(b * A_ + a) * N_ + s] = acc;
}

extern "C" void kernel_launch(void* const* d_in, const int* in_sizes, int n_in,
                              void* d_out, int out_size)
{
    const float* imgs   = (const float*)d_in[0];
    const float* angles = (const float*)d_in[1];
    float*       out    = (float*)d_out;

    cudaFuncSetAttribute(radon_kernel,
                         cudaFuncAttributeMaxDynamicSharedMemorySize,
                         SMEM_WORDS * (int)sizeof(float));

    const int blocks = B_ * (A_ / 2);   // 720
    radon_kernel<<<blocks, 512, SMEM_WORDS * sizeof(float)>>>(imgs, angles, out);
}

// round 7
// speedup vs baseline: 2.0140x; 1.0825x over previous
#include <cuda_runtime.h>

// Radon forward projection, phase-split formulation.
// out[b,a,s] = sum_t bilinear(imgs[b], x(s,t), y(s,t)),
// x = s*cos - t*sin + c ; y = s*sin + t*cos + c ; c = 127.5.
//
// Kernel 1: block = (b, angle-pair, phase), 5760 blocks, 512 threads
// (2 angles x 256 detectors). Phase p owns y0i in its 32-row band; the block
// stages a 34-row x 287-col tile (guard rows/cols zero) in 39 KB static SMEM
// -> 4 CTAs/SM, 64 warps (occ cap 100%), and fine grid kills the wave tail.
// Each block writes 512 partial sums; kernel 2 reduces 8 phases per output
// in a fixed order (deterministic).
//
// Ownership is EXACT: band p owns yv = y+1 in [lo_p, hi_p) with integer
// float bounds, tested on the SAME fmaf(tf,ca,ys1) everywhere (monotone in
// t: conservative analytic entry, exact entry scan, exit break).
// Guard-shifted coords xv = x+5, yv = y+1 make (int) trunc == floor, no clamps:
// the analytic x-window guarantees xv > -0.02 and x outside [-1,257) lands on
// zero guard columns (exactly 0 contribution).

#define B_ 8
#define N_ 256
#define A_ 180

constexpr int PAIRS      = A_ / 2;           // 90
constexpr int PHASES     = 8;
constexpr int BAND       = 32;
constexpr int STRIDE     = 287;              // == 31 mod 32 -> bank = xi - yr
constexpr int TROWS      = BAND + 2;         // 34
constexpr int SMEM_WORDS = STRIDE * TROWS;   // 9,758 floats = 39,032 B
constexpr int NBLK       = B_ * PAIRS * PHASES;  // 5760

__device__ float g_partial[NBLK * 512];      // 11.8 MB static scratch

__global__ __launch_bounds__(512, 4)
void radon_phase_kernel(const float* __restrict__ imgs,
                        const float* __restrict__ angles)
{
    __shared__ float tile[SMEM_WORDS];

    const int tid  = threadIdx.x;
    const int blk  = blockIdx.x;
    const int p    = blk & 7;                // phase
    const int bp   = blk >> 3;               // b*PAIRS + pair
    const int b    = bp / PAIRS;
    const int pr   = bp - b * PAIRS;
    const int al   = tid >> 8;               // which angle of the pair
    const int s    = tid & 255;              // detector index
    const int warp = tid >> 5;
    const int lane = tid & 31;

    const float ang = angles[pr * 2 + al];
    const float ca  = cosf(ang);
    const float sa  = sinf(ang);
    const float sf  = (float)s - 127.5f;
    const float xs  = fmaf(sf, ca, 127.5f);
    const float xs5 = xs + 5.0f;             // guard-shifted x origin
    const float ys1 = fmaf(sf, sa, 127.5f) + 1.0f;  // guard-shifted y origin
    const float nsa = -sa;
    const bool  up  = (ca >= 0.0f);          // yv non-decreasing in t?

    // yv endpoints (same fmaf form as the loop) for exact band pre-check
    const float yA    = fmaf(-127.5f, ca, ys1);
    const float yB    = fmaf( 127.5f, ca, ys1);
    const float yvmin = fminf(yA, yB);
    const float yvmax = fmaxf(yA, yB);

    // Owned band in yv space: floor(yv) in [lo, hi-1].
    // p=0 owns y0i in [-1,31] -> yv in [0,33); p>0 owns y0i in
    // [32p, 32p+31] -> yv in [32p+1, 32p+33). Exact integer float bounds.
    const float lo = (p == 0) ? 0.0f : (float)(BAND * p + 1);
    const float hi = (float)(BAND * p + 33);

    // block-wide empty-band early out (skip staging entirely)
    const bool hit = (yvmax >= lo) & (yvmin < hi);
    if (!__syncthreads_or(hit)) {
        g_partial[blk * 512 + tid] = 0.0f;
        return;
    }

    // ---- stage tile: warp per row, lanes over columns; zeros in guards
    const int base = BAND * p - 1;           // image row of tile row 0
    const float* __restrict__ img = imgs + b * N_ * N_;
    for (int r = warp; r < TROWS; r += 16) {
        const int ir = base + r;
        float* dst = tile + r * STRIDE;
        if ((unsigned)ir < (unsigned)N_) {
            const float* src = img + ir * N_;
            for (int c = lane; c < STRIDE; c += 32) {
                int ic = c - 5;
                dst[c] = ((unsigned)ic < (unsigned)N_) ? src[ic] : 0.0f;
            }
        } else {
            for (int c = lane; c < STRIDE; c += 32) dst[c] = 0.0f;
        }
    }
    __syncthreads();

    float acc = 0.0f;

    if (hit) {
        // analytic helpers (conservative only; exactness from in-loop tests)
        const float inv_ca = 1.0f / ((ca == 0.0f) ? 1e-30f : ca);
        const float inv_sa = 1.0f / ((sa == 0.0f) ? 1e-30f : sa);

        // x-window: x outside (-3,259) padded +-2 -> both sampled cols are
        // staged zeros -> exactly 0 contribution. Inside-window xv = x+5 in
        // (-0.01, 266.01), all staged (STRIDE=287 > 267).
        float tca = (xs + 3.0f)   * inv_sa;
        float tcb = (xs - 259.0f) * inv_sa;
        const int txlo = (int)fmaxf(floorf(fminf(tca, tcb) + 127.5f) - 2.0f, 0.0f);
        const int txhi = (int)fminf(ceilf (fmaxf(tca, tcb) + 127.5f) + 2.0f, 255.0f);

        // conservative analytic entry (pad -2, never late)
        const float Lb = up ? lo : hi;
        float t_ent = fmaf(Lb - ys1, inv_ca, 127.5f);
        int t = max((int)fmaxf(fminf(floorf(t_ent) - 2.0f, 255.0f), 0.0f), txlo);
        float tf = (float)t - 127.5f;

        // exact entry scan: advance until yv enters the band
        for (; t <= txhi; ++t, tf += 1.0f) {
            float yv = fmaf(tf, ca, ys1);
            if (up ? (yv >= lo) : (yv < hi)) break;
        }

        // fold rowoff into the base pointer: row index used is trunc(yv)
        const float* __restrict__ tb = tile - (BAND * p) * STRIDE;

        // main loop: only the exit test remains
        #pragma unroll 2
        for (; t <= txhi; ++t, tf += 1.0f) {
            float yv = fmaf(tf, ca, ys1);
            if (up ? (yv >= hi) : (yv < lo)) break;   // passed band: done

            float xv = fmaf(tf, nsa, xs5);
            int yi = (int)yv;                  // trunc == floor (yv >= 0)
            int xi = (int)xv;
            float wy = yv - (float)yi;
            float wx = xv - (float)xi;

            const float* ptr = tb + yi * STRIDE + xi;
            float a00 = ptr[0];
            float a01 = ptr[1];
            float a10 = ptr[STRIDE];
            float a11 = ptr[STRIDE + 1];

            float h0 = fmaf(wx, a01 - a00, a00);
            float h1 = fmaf(wx, a11 - a10, a10);
            acc += fmaf(wy, h1 - h0, h0);
        }
    }

    g_partial[blk * 512 + tid] = acc;
}

// Kernel 2: out[b, 2*pr+al, s] = sum_p partial[((b*90+pr)*8+p)*512 + al*256 + s]
__global__ __launch_bounds__(256)
void radon_reduce_kernel(float* __restrict__ out)
{
    const int o  = blockIdx.x * 256 + threadIdx.x;   // 368,640 outputs
    const int s  = o & 255;
    const int ba = o >> 8;
    const int a  = ba % A_;
    const int b  = ba / A_;
    const int pr = a >> 1;
    const int al = a & 1;

    const float* p = g_partial + ((b * PAIRS + pr) * PHASES) * 512 + al * 256 + s;
    float acc = 0.0f;
    #pragma unroll
    for (int k = 0; k < PHASES; ++k) acc += p[k * 512];
    out[o] = acc;
}

extern "C" void kernel_launch(void* const* d_in, const int* in_sizes, int n_in,
                              void* d_out, int out_size)
{
    const float* imgs   = (const float*)d_in[0];
    const float* angles = (const float*)d_in[1];
    float*       out    = (float*)d_out;

    radon_phase_kernel<<<NBLK, 512>>>(imgs, angles);
    radon_reduce_kernel<<<(B_ * A_ * N_) / 256, 256>>>(out);
}

// round 9
// speedup vs baseline: 2.2031x; 1.0939x over previous
#include <cuda_runtime.h>

// Radon forward projection, phase-split + row-pair-float2 formulation.
// out[b,a,s] = sum_t bilinear(imgs[b], x(s,t), y(s,t)),
// x = s*cos - t*sin + c ; y = s*sin + t*cos + c ; c = 127.5.
//
// Kernel 1: block = (b, angle-pair, phase), 6480 blocks, 512 threads
// (2 angles x 256 detectors). Phase p owns y0i in a 31-row band (32 for p0).
// Tile rows are float2 ROW PAIRS: tile[r][x] = (img[base+r][x], img[base+r+1][x])
// so each bilinear sample needs only 2x LDS.64 instead of 4x LDS.32.
// 32 rows x 287 float2 = 73.5 KB dynamic smem -> 3 CTAs/SM.
//
// Ownership is EXACT: band p owns yv = y+1 in [lo_p, hi_p), integer float
// bounds, tested on the SAME fmaf(tf,ca,ys1) everywhere. Monotone yv(t):
// conservative analytic entry/exit estimates refined by exact scans -> a
// branchless counted inner loop. CRITICAL (R7 bugfix): the exit-scan start is
// clamped to txhi+1, so when the band exit lies beyond the x-window the count
// is txhi+1-t (window-bounded), never past it — all counted iterations are
// provably in-band AND in-window, so every smem access is staged.
// Guard-shifted coords xv = x+5 (trunc; eps<0 lands on zero guard cols),
// yv = y+1 >= 0 in-band. x outside the window hits zero guard cols -> 0.

#define B_ 8
#define N_ 256
#define A_ 180

constexpr int PAIRS      = A_ / 2;            // 90
constexpr int BAND       = 31;
constexpr int PHASES     = 9;                 // ceil(257/31)
constexpr int STRIDE     = 287;               // float2 elements per tile row
constexpr int TROWS      = 32;                // row-pairs: covers BAND+1 rows
constexpr int SMEM_BYTES = TROWS * STRIDE * 8;    // 73,472 B
constexpr int NBLK       = B_ * PAIRS * PHASES;   // 6480

__device__ float g_partial[NBLK * 512];       // 13.3 MB static scratch

__global__ __launch_bounds__(512, 3)
void radon_phase_kernel(const float* __restrict__ imgs,
                        const float* __restrict__ angles)
{
    extern __shared__ float2 tile[];

    const int tid  = threadIdx.x;
    const int blk  = blockIdx.x;
    const int p    = blk % PHASES;
    const int bp   = blk / PHASES;            // b*PAIRS + pair
    const int b    = bp / PAIRS;
    const int pr   = bp - b * PAIRS;
    const int al   = tid >> 8;                // which angle of the pair
    const int s    = tid & 255;               // detector index
    const int warp = tid >> 5;
    const int lane = tid & 31;

    const float ang = angles[pr * 2 + al];
    const float ca  = cosf(ang);
    const float sa  = sinf(ang);
    const float sf  = (float)s - 127.5f;
    const float xs  = fmaf(sf, ca, 127.5f);
    const float xs5 = xs + 5.0f;              // guard-shifted x origin
    const float ys1 = fmaf(sf, sa, 127.5f) + 1.0f;   // guard-shifted y origin
    const float nsa = -sa;
    const bool  up  = (ca >= 0.0f);           // yv non-decreasing in t?

    // yv endpoints (same fmaf form as the loop) for exact band pre-check
    const float yA    = fmaf(-127.5f, ca, ys1);
    const float yB    = fmaf( 127.5f, ca, ys1);
    const float yvmin = fminf(yA, yB);
    const float yvmax = fmaxf(yA, yB);

    // Owned band in yv space: floor(yv) in [lo, hi-1].
    // p=0: y0i in [-1,30]  -> yv in [0,32).
    // p>0: y0i in [31p, 31p+30] -> yv in [31p+1, 31p+32). Exact int bounds.
    const float lo = (p == 0) ? 0.0f : (float)(BAND * p + 1);
    const float hi = (float)(BAND * p + 32);

    // block-wide empty-band early out (skip staging entirely)
    const bool hit = (yvmax >= lo) & (yvmin < hi);
    if (!__syncthreads_or(hit)) {
        g_partial[blk * 512 + tid] = 0.0f;
        return;
    }

    // ---- stage row-pair tile: tile[r][c] = (img[base+r][c-5], img[base+r+1][c-5])
    const int base = BAND * p - 1;            // image row of tile row r=0 (.x half)
    const float* __restrict__ img = imgs + b * N_ * N_;
    for (int r = warp; r < TROWS; r += 16) {
        const int ir0 = base + r;
        const int ir1 = ir0 + 1;
        const bool v0ok = (unsigned)ir0 < (unsigned)N_;
        const bool v1ok = (unsigned)ir1 < (unsigned)N_;
        const float* s0 = img + ir0 * N_;
        const float* s1 = img + ir1 * N_;
        float2* dst = tile + r * STRIDE;
        for (int c = lane; c < STRIDE; c += 32) {
            int ic = c - 5;
            bool cin = (unsigned)ic < (unsigned)N_;
            float v0 = (v0ok && cin) ? s0[ic] : 0.0f;
            float v1 = (v1ok && cin) ? s1[ic] : 0.0f;
            dst[c] = make_float2(v0, v1);
        }
    }
    __syncthreads();

    float acc = 0.0f;

    if (hit) {
        // analytic helpers (conservative only; exactness from scans)
        const float inv_ca = 1.0f / ((ca == 0.0f) ? 1e-30f : ca);
        const float inv_sa = 1.0f / ((sa == 0.0f) ? 1e-30f : sa);

        // x-window: x outside (-3,259) padded +-2 -> both sampled cols are
        // zero guards -> exactly 0. Inside: xv = x+5 in (-0.01, 266.01).
        float tca = (xs + 3.0f)   * inv_sa;
        float tcb = (xs - 259.0f) * inv_sa;
        const int txlo = (int)fmaxf(floorf(fminf(tca, tcb) + 127.5f) - 2.0f, 0.0f);
        const int txhi = (int)fminf(ceilf (fmaxf(tca, tcb) + 127.5f) + 2.0f, 255.0f);

        // conservative analytic entry (pad -2, never late), exact entry scan
        const float Lb = up ? lo : hi;
        float t_ent = fmaf(Lb - ys1, inv_ca, 127.5f);
        int t = max((int)fmaxf(fminf(floorf(t_ent) - 2.0f, 255.0f), 0.0f), txlo);
        float tf = (float)t - 127.5f;
        for (; t <= txhi; ++t, tf += 1.0f) {
            float yv = fmaf(tf, ca, ys1);
            if (up ? (yv >= lo) : (yv < hi)) break;
        }

        int n = 0;
        if (t <= txhi) {
            // conservative analytic exit (pad -2, never late), exact exit
            // scan. BUGFIX vs R7: clamp the scan start to txhi+1 (in float,
            // before the int cast) so a window-limited ray counts exactly
            // txhi+1-t iterations and never runs past the staged window.
            const float Ub = up ? hi : lo;
            float t_xt = fmaf(Ub - ys1, inv_ca, 127.5f);
            float te_f = fmaxf(fminf(floorf(t_xt) - 2.0f, (float)(txhi + 1)),
                               (float)t);
            int te = (int)te_f;
            float tfe = (float)te - 127.5f;
            for (; te <= txhi; ++te, tfe += 1.0f) {
                float yv = fmaf(tfe, ca, ys1);
                if (up ? (yv >= hi) : (yv < lo)) break;   // first t past band
            }
            n = te - t;     // owned iterations: t .. te-1 (in-band, in-window)
        }

        // fold the band row offset into the base pointer:
        // row index = floor(yv) - 31p; idx = (floor(yv)-31p)*287 + xi
        const float2* __restrict__ tb = tile - (BAND * p) * STRIDE;

        #pragma unroll 4
        for (int k = 0; k < n; ++k) {
            float yv = fmaf(tf, ca, ys1);
            float xv = fmaf(tf, nsa, xs5);
            float fy = truncf(yv);            // yv >= 0 in-band: trunc == floor
            float fx = truncf(xv);            // eps<0 -> col 0 zero guard
            float wy = yv - fy;
            float wx = xv - fx;
            int idx  = (int)fmaf(fy, (float)STRIDE, fx);   // exact (< 2^24)

            float2 v0 = tb[idx];              // (a00, a10)
            float2 v1 = tb[idx + 1];          // (a01, a11)

            float h0 = fmaf(wx, v1.x - v0.x, v0.x);
            float h1 = fmaf(wx, v1.y - v0.y, v0.y);
            acc += fmaf(wy, h1 - h0, h0);
            tf += 1.0f;
        }
    }

    g_partial[blk * 512 + tid] = acc;
}

// Kernel 2: out[b, 2*pr+al, s] = sum_p partial[((b*90+pr)*9+p)*512 + al*256 + s]
__global__ __launch_bounds__(256)
void radon_reduce_kernel(float* __restrict__ out)
{
    const int o  = blockIdx.x * 256 + threadIdx.x;   // 368,640 outputs
    const int s  = o & 255;
    const int ba = o >> 8;
    const int a  = ba % A_;
    const int b  = ba / A_;
    const int pr = a >> 1;
    const int al = a & 1;

    const float* p = g_partial + ((b * PAIRS + pr) * PHASES) * 512 + al * 256 + s;
    float acc = 0.0f;
    #pragma unroll
    for (int k = 0; k < PHASES; ++k) acc += p[k * 512];
    out[o] = acc;
}

extern "C" void kernel_launch(void* const* d_in, const int* in_sizes, int n_in,
                              void* d_out, int out_size)
{
    const float* imgs   = (const float*)d_in[0];
    const float* angles = (const float*)d_in[1];
    float*       out    = (float*)d_out;

    cudaFuncSetAttribute(radon_phase_kernel,
                         cudaFuncAttributeMaxDynamicSharedMemorySize, SMEM_BYTES);

    radon_phase_kernel<<<NBLK, 512, SMEM_BYTES>>>(imgs, angles);
    radon_reduce_kernel<<<(B_ * A_ * N_) / 256, 256>>>(out);
}